// round 1
// baseline (speedup 1.0000x reference)
#include <cuda_runtime.h>

#define N_NODES 100000
#define N_EDGES 1600000
#define HDIM 128
#define EDIM 32
#define KDIM (2 * HDIM + EDIM)   // 288: [x | Sx | Se]
#define TM 32                    // nodes per GEMM tile
#define GEMM_THREADS 256
#define GEMM_SMEM_FLOATS (KDIM * HDIM + TM * KDIM)
#define GEMM_SMEM_BYTES (GEMM_SMEM_FLOATS * 4)

// Scratch (allocation-free rule: __device__ globals)
__device__ float g_Sx[N_NODES * HDIM];   // segment_sum(x[src], dst)
__device__ float g_Se[N_NODES * EDIM];   // segment_sum(edge_attr, dst)
__device__ float g_deg[N_NODES];         // in-degree (for b_msg term)

// ---------------------------------------------------------------------------
// Kernel 1: zero the scratch buffers (graph replays require re-zeroing)
// ---------------------------------------------------------------------------
__global__ void zero_scratch_kernel() {
    int tid = blockIdx.x * blockDim.x + threadIdx.x;
    int stride = gridDim.x * blockDim.x;
    float4 z = make_float4(0.f, 0.f, 0.f, 0.f);
    float4* sx = reinterpret_cast<float4*>(g_Sx);
    for (int i = tid; i < N_NODES * HDIM / 4; i += stride) sx[i] = z;
    float4* se = reinterpret_cast<float4*>(g_Se);
    for (int i = tid; i < N_NODES * EDIM / 4; i += stride) se[i] = z;
    for (int i = tid; i < N_NODES; i += stride) g_deg[i] = 0.f;
}

// ---------------------------------------------------------------------------
// Kernel 2: edge scatter. One warp per edge:
//   lanes 0..31: float4 chunk of x[src] row -> red.v4.f32 into g_Sx[dst]
//   lanes 0..7 : float4 chunk of edge_attr  -> red.v4.f32 into g_Se[dst]
//   lane 8     : degree count
// ---------------------------------------------------------------------------
__global__ void scatter_kernel(const float* __restrict__ x,
                               const int* __restrict__ ei,
                               const float* __restrict__ ea) {
    int gw = (blockIdx.x * blockDim.x + threadIdx.x) >> 5;
    int lane = threadIdx.x & 31;
    int nw = (gridDim.x * blockDim.x) >> 5;
    for (int e = gw; e < N_EDGES; e += nw) {
        int src = __ldg(&ei[e]);
        int dst = __ldg(&ei[N_EDGES + e]);

        // x[src] row: 32 lanes x float4 = 512B coalesced
        float4 v = reinterpret_cast<const float4*>(x + (size_t)src * HDIM)[lane];
        float* o = g_Sx + (size_t)dst * HDIM + lane * 4;
        asm volatile("red.global.add.v4.f32 [%0], {%1,%2,%3,%4};"
                     :: "l"(o), "f"(v.x), "f"(v.y), "f"(v.z), "f"(v.w)
                     : "memory");

        if (lane < 8) {
            float4 w = reinterpret_cast<const float4*>(ea + (size_t)e * EDIM)[lane];
            float* o2 = g_Se + (size_t)dst * EDIM + lane * 4;
            asm volatile("red.global.add.v4.f32 [%0], {%1,%2,%3,%4};"
                         :: "l"(o2), "f"(w.x), "f"(w.y), "f"(w.z), "f"(w.w)
                         : "memory");
        } else if (lane == 8) {
            atomicAdd(&g_deg[dst], 1.0f);
        }
    }
}

// ---------------------------------------------------------------------------
// Kernel 3: fused node GEMM + bias + ReLU.
//   out[n,:] = relu( [x[n] | Sx[n] | Se[n]] @ W  + b_self + deg[n]*b_msg )
// where W (288x128) = [W_self ; W_msg] staged fully in smem.
// Tile: 32 nodes per CTA iteration, 256 threads: thread (j = tid&127,
// group = tid>>7) computes 16 nodes' output column j.
// ---------------------------------------------------------------------------
__global__ void __launch_bounds__(GEMM_THREADS, 1)
node_gemm_kernel(const float* __restrict__ x,
                 const float* __restrict__ Wself,
                 const float* __restrict__ bself,
                 const float* __restrict__ Wmsg,
                 const float* __restrict__ bmsg,
                 float* __restrict__ out) {
    extern __shared__ float sh[];
    float* Wsh = sh;                      // [KDIM][HDIM]
    float* insh = sh + KDIM * HDIM;       // [TM][KDIM] node-major
    __shared__ float bs[HDIM];
    __shared__ float bm[HDIM];

    for (int i = threadIdx.x; i < HDIM * HDIM; i += GEMM_THREADS)
        Wsh[i] = Wself[i];
    for (int i = threadIdx.x; i < (HDIM + EDIM) * HDIM; i += GEMM_THREADS)
        Wsh[HDIM * HDIM + i] = Wmsg[i];
    if (threadIdx.x < HDIM) {
        bs[threadIdx.x] = bself[threadIdx.x];
        bm[threadIdx.x] = bmsg[threadIdx.x];
    }
    __syncthreads();

    const int j = threadIdx.x & 127;
    const int group = threadIdx.x >> 7;   // 0 or 1 -> 16 nodes each
    const int n_tiles = N_NODES / TM;     // 3125 exactly

    for (int tile = blockIdx.x; tile < n_tiles; tile += gridDim.x) {
        const int n0 = tile * TM;

        __syncthreads();  // previous tile's insh reads done
        // Stage the 32x288 virtual concat tile (coalesced global reads)
        for (int idx = threadIdx.x; idx < TM * KDIM; idx += GEMM_THREADS) {
            int n = idx / KDIM;
            int k = idx - n * KDIM;
            int gn = n0 + n;
            float v;
            if (k < HDIM)            v = x[(size_t)gn * HDIM + k];
            else if (k < 2 * HDIM)   v = g_Sx[(size_t)gn * HDIM + (k - HDIM)];
            else                     v = g_Se[(size_t)gn * EDIM + (k - 2 * HDIM)];
            insh[n * KDIM + k] = v;
        }
        __syncthreads();

        float acc[16];
#pragma unroll
        for (int n = 0; n < 16; n++) acc[n] = 0.f;

        for (int k = 0; k < KDIM; k += 4) {
            float w0 = Wsh[(k + 0) * HDIM + j];
            float w1 = Wsh[(k + 1) * HDIM + j];
            float w2 = Wsh[(k + 2) * HDIM + j];
            float w3 = Wsh[(k + 3) * HDIM + j];
#pragma unroll
            for (int n = 0; n < 16; n++) {
                // broadcast LDS.128: same address across the warp
                float4 iv = *reinterpret_cast<const float4*>(
                    &insh[(group * 16 + n) * KDIM + k]);
                acc[n] = fmaf(iv.x, w0, acc[n]);
                acc[n] = fmaf(iv.y, w1, acc[n]);
                acc[n] = fmaf(iv.z, w2, acc[n]);
                acc[n] = fmaf(iv.w, w3, acc[n]);
            }
        }

#pragma unroll
        for (int n = 0; n < 16; n++) {
            int gn = n0 + group * 16 + n;
            float r = acc[n] + bs[j] + g_deg[gn] * bm[j];
            out[(size_t)gn * HDIM + j] = fmaxf(r, 0.f);
        }
    }
}

// ---------------------------------------------------------------------------
extern "C" void kernel_launch(void* const* d_in, const int* in_sizes, int n_in,
                              void* d_out, int out_size) {
    const float* x     = (const float*)d_in[0];
    const int*   ei    = (const int*)  d_in[1];
    const float* ea    = (const float*)d_in[2];
    const float* Wself = (const float*)d_in[3];
    const float* bself = (const float*)d_in[4];
    const float* Wmsg  = (const float*)d_in[5];
    const float* bmsg  = (const float*)d_in[6];
    float* out = (float*)d_out;

    cudaFuncSetAttribute(node_gemm_kernel,
                         cudaFuncAttributeMaxDynamicSharedMemorySize,
                         GEMM_SMEM_BYTES);

    zero_scratch_kernel<<<2048, 256>>>();
    scatter_kernel<<<4096, 256>>>(x, ei, ea);
    node_gemm_kernel<<<148, GEMM_THREADS, GEMM_SMEM_BYTES>>>(
        x, Wself, bself, Wmsg, bmsg, out);
}

// round 2
// speedup vs baseline: 1.0973x; 1.0973x over previous
#include <cuda_runtime.h>

#define N_NODES 100000
#define N_EDGES 1600000
#define HDIM 128
#define EDIM 32
#define KDIM (2 * HDIM + EDIM)   // 288: [x | Sx | Se]
#define TM 32
#define GEMM_THREADS 256
#define GEMM_SMEM_FLOATS (KDIM * HDIM + TM * KDIM)
#define GEMM_SMEM_BYTES (GEMM_SMEM_FLOATS * 4)
#define NB 98                    // scan blocks: ceil(100000/1024)

// Scratch (__device__ globals: allocation-free rule)
__device__ float g_Sx[N_NODES * HDIM];   // segment_sum(x[src], dst)
__device__ float g_Se[N_NODES * EDIM];   // segment_sum(edge_attr, dst)
__device__ int   g_deg[N_NODES];         // in-degree histogram
__device__ int   g_off[N_NODES];         // CSR offsets (excl, then incl-end after reorder)
__device__ int   g_bsum[NB];             // scan block sums
__device__ int2  g_rec[N_EDGES];         // (src, edge_id) sorted by dst bucket

// ---------------------------------------------------------------------------
// 1) zero histogram (only per-replay state that needs re-init)
// ---------------------------------------------------------------------------
__global__ void zero_hist_kernel() {
    int i = blockIdx.x * blockDim.x + threadIdx.x;
    if (i < N_NODES) g_deg[i] = 0;
}

// ---------------------------------------------------------------------------
// 2) degree histogram
// ---------------------------------------------------------------------------
__global__ void hist_kernel(const int* __restrict__ ei) {
    int e = blockIdx.x * blockDim.x + threadIdx.x;
    if (e < N_EDGES) atomicAdd(&g_deg[__ldg(&ei[N_EDGES + e])], 1);
}

// ---------------------------------------------------------------------------
// 3) exclusive scan of degrees -> g_off  (3 kernels)
// ---------------------------------------------------------------------------
__device__ __forceinline__ int warp_incl_scan(int v, int lane) {
#pragma unroll
    for (int d = 1; d < 32; d <<= 1) {
        int t = __shfl_up_sync(0xffffffffu, v, d);
        if (lane >= d) v += t;
    }
    return v;
}

__global__ void scan1_kernel() {
    __shared__ int wsum[32];
    int i = blockIdx.x * 1024 + threadIdx.x;
    int lane = threadIdx.x & 31, w = threadIdx.x >> 5;
    int v = (i < N_NODES) ? g_deg[i] : 0;
    int inc = warp_incl_scan(v, lane);
    if (lane == 31) wsum[w] = inc;
    __syncthreads();
    if (w == 0) {
        int s = wsum[lane];
        int si = warp_incl_scan(s, lane);
        wsum[lane] = si - s;           // exclusive warp offsets
    }
    __syncthreads();
    int excl = inc - v + wsum[w];
    if (i < N_NODES) g_off[i] = excl;
    if (threadIdx.x == 1023) g_bsum[blockIdx.x] = excl + v;  // block total
}

__global__ void scan2_kernel() {
    __shared__ int wsum[4];
    int i = threadIdx.x;                // 128 threads
    int lane = i & 31, w = i >> 5;
    int v = (i < NB) ? g_bsum[i] : 0;
    int inc = warp_incl_scan(v, lane);
    if (lane == 31) wsum[w] = inc;
    __syncthreads();
    if (i == 0) {
        int c = 0;
#pragma unroll
        for (int k = 0; k < 4; k++) { int t = wsum[k]; wsum[k] = c; c += t; }
    }
    __syncthreads();
    if (i < NB) g_bsum[i] = inc - v + wsum[w];
}

__global__ void scan3_kernel() {
    int i = blockIdx.x * 1024 + threadIdx.x;
    if (i < N_NODES) g_off[i] += g_bsum[blockIdx.x];
}

// ---------------------------------------------------------------------------
// 4) reorder edges into dst-buckets. After this, g_off[n] = inclusive end of
//    bucket n (start of n = g_off[n-1], or 0 for n=0).
// ---------------------------------------------------------------------------
__global__ void reorder_kernel(const int* __restrict__ ei) {
    int e = blockIdx.x * blockDim.x + threadIdx.x;
    if (e >= N_EDGES) return;
    int src = __ldg(&ei[e]);
    int dst = __ldg(&ei[N_EDGES + e]);
    int pos = atomicAdd(&g_off[dst], 1);
    g_rec[pos] = make_int2(src, e);
}

// ---------------------------------------------------------------------------
// 5) gather-accumulate: one warp per dst node, accumulate in registers,
//    single coalesced store. NO atomics.
// ---------------------------------------------------------------------------
__global__ void __launch_bounds__(256)
gather_kernel(const float* __restrict__ x, const float* __restrict__ ea) {
    int gw   = (blockIdx.x * blockDim.x + threadIdx.x) >> 5;
    int lane = threadIdx.x & 31;
    int nw   = (gridDim.x * blockDim.x) >> 5;

    for (int n = gw; n < N_NODES; n += nw) {
        int beg = (n == 0) ? 0 : __ldg(&g_off[n - 1]);
        int end = __ldg(&g_off[n]);

        float4 ax = make_float4(0.f, 0.f, 0.f, 0.f);
        float4 ae = make_float4(0.f, 0.f, 0.f, 0.f);

        int i = beg;
        // 2-wide software pipeline: two independent gathers in flight
        for (; i + 1 < end; i += 2) {
            int2 r0 = __ldg(&g_rec[i]);
            int2 r1 = __ldg(&g_rec[i + 1]);
            float4 v0 = __ldg(&reinterpret_cast<const float4*>(
                                  x + (size_t)r0.x * HDIM)[lane]);
            float4 v1 = __ldg(&reinterpret_cast<const float4*>(
                                  x + (size_t)r1.x * HDIM)[lane]);
            ax.x += v0.x + v1.x; ax.y += v0.y + v1.y;
            ax.z += v0.z + v1.z; ax.w += v0.w + v1.w;
            if (lane < 8) {
                float4 w0 = __ldg(&reinterpret_cast<const float4*>(
                                      ea + (size_t)r0.y * EDIM)[lane]);
                float4 w1 = __ldg(&reinterpret_cast<const float4*>(
                                      ea + (size_t)r1.y * EDIM)[lane]);
                ae.x += w0.x + w1.x; ae.y += w0.y + w1.y;
                ae.z += w0.z + w1.z; ae.w += w0.w + w1.w;
            }
        }
        if (i < end) {
            int2 r0 = __ldg(&g_rec[i]);
            float4 v0 = __ldg(&reinterpret_cast<const float4*>(
                                  x + (size_t)r0.x * HDIM)[lane]);
            ax.x += v0.x; ax.y += v0.y; ax.z += v0.z; ax.w += v0.w;
            if (lane < 8) {
                float4 w0 = __ldg(&reinterpret_cast<const float4*>(
                                      ea + (size_t)r0.y * EDIM)[lane]);
                ae.x += w0.x; ae.y += w0.y; ae.z += w0.z; ae.w += w0.w;
            }
        }

        reinterpret_cast<float4*>(g_Sx + (size_t)n * HDIM)[lane] = ax;
        if (lane < 8)
            reinterpret_cast<float4*>(g_Se + (size_t)n * EDIM)[lane] = ae;
    }
}

// ---------------------------------------------------------------------------
// 6) fused node GEMM + bias + ReLU (unchanged from R1, deg now int)
// ---------------------------------------------------------------------------
__global__ void __launch_bounds__(GEMM_THREADS, 1)
node_gemm_kernel(const float* __restrict__ x,
                 const float* __restrict__ Wself,
                 const float* __restrict__ bself,
                 const float* __restrict__ Wmsg,
                 const float* __restrict__ bmsg,
                 float* __restrict__ out) {
    extern __shared__ float sh[];
    float* Wsh  = sh;                      // [KDIM][HDIM]
    float* insh = sh + KDIM * HDIM;        // [TM][KDIM]
    __shared__ float bs[HDIM];
    __shared__ float bm[HDIM];

    for (int i = threadIdx.x; i < HDIM * HDIM; i += GEMM_THREADS)
        Wsh[i] = Wself[i];
    for (int i = threadIdx.x; i < (HDIM + EDIM) * HDIM; i += GEMM_THREADS)
        Wsh[HDIM * HDIM + i] = Wmsg[i];
    if (threadIdx.x < HDIM) {
        bs[threadIdx.x] = bself[threadIdx.x];
        bm[threadIdx.x] = bmsg[threadIdx.x];
    }
    __syncthreads();

    const int j = threadIdx.x & 127;
    const int group = threadIdx.x >> 7;
    const int n_tiles = N_NODES / TM;      // 3125 exactly

    for (int tile = blockIdx.x; tile < n_tiles; tile += gridDim.x) {
        const int n0 = tile * TM;

        __syncthreads();
        for (int idx = threadIdx.x; idx < TM * KDIM; idx += GEMM_THREADS) {
            int n = idx / KDIM;
            int k = idx - n * KDIM;
            int gn = n0 + n;
            float v;
            if (k < HDIM)          v = x[(size_t)gn * HDIM + k];
            else if (k < 2 * HDIM) v = g_Sx[(size_t)gn * HDIM + (k - HDIM)];
            else                   v = g_Se[(size_t)gn * EDIM + (k - 2 * HDIM)];
            insh[n * KDIM + k] = v;
        }
        __syncthreads();

        float acc[16];
#pragma unroll
        for (int n = 0; n < 16; n++) acc[n] = 0.f;

        for (int k = 0; k < KDIM; k += 4) {
            float w0 = Wsh[(k + 0) * HDIM + j];
            float w1 = Wsh[(k + 1) * HDIM + j];
            float w2 = Wsh[(k + 2) * HDIM + j];
            float w3 = Wsh[(k + 3) * HDIM + j];
#pragma unroll
            for (int n = 0; n < 16; n++) {
                float4 iv = *reinterpret_cast<const float4*>(
                    &insh[(group * 16 + n) * KDIM + k]);
                acc[n] = fmaf(iv.x, w0, acc[n]);
                acc[n] = fmaf(iv.y, w1, acc[n]);
                acc[n] = fmaf(iv.z, w2, acc[n]);
                acc[n] = fmaf(iv.w, w3, acc[n]);
            }
        }

#pragma unroll
        for (int n = 0; n < 16; n++) {
            int gn = n0 + group * 16 + n;
            float r = acc[n] + bs[j] + (float)g_deg[gn] * bm[j];
            out[(size_t)gn * HDIM + j] = fmaxf(r, 0.f);
        }
    }
}

// ---------------------------------------------------------------------------
extern "C" void kernel_launch(void* const* d_in, const int* in_sizes, int n_in,
                              void* d_out, int out_size) {
    const float* x     = (const float*)d_in[0];
    const int*   ei    = (const int*)  d_in[1];
    const float* ea    = (const float*)d_in[2];
    const float* Wself = (const float*)d_in[3];
    const float* bself = (const float*)d_in[4];
    const float* Wmsg  = (const float*)d_in[5];
    const float* bmsg  = (const float*)d_in[6];
    float* out = (float*)d_out;

    cudaFuncSetAttribute(node_gemm_kernel,
                         cudaFuncAttributeMaxDynamicSharedMemorySize,
                         GEMM_SMEM_BYTES);

    zero_hist_kernel<<<NB, 1024>>>();
    hist_kernel<<<(N_EDGES + 511) / 512, 512>>>(ei);
    scan1_kernel<<<NB, 1024>>>();
    scan2_kernel<<<1, 128>>>();
    scan3_kernel<<<NB, 1024>>>();
    reorder_kernel<<<(N_EDGES + 511) / 512, 512>>>(ei);
    gather_kernel<<<148 * 8, 256>>>(x, ea);
    node_gemm_kernel<<<148, GEMM_THREADS, GEMM_SMEM_BYTES>>>(
        x, Wself, bself, Wmsg, bmsg, out);
}

// round 5
// speedup vs baseline: 3.2618x; 2.9726x over previous
#include <cuda_runtime.h>
#include <cuda_bf16.h>
#include <cstdint>

#define N_NODES 100000
#define N_EDGES 1600000
#define HDIM 128
#define EDIM 32
#define KDIM 288                 // 128 + 128 + 32, = 9 * 32 exactly
#define NCHUNK 9
#define N_TILES ((N_NODES + 127) / 128)   // 782
#define NB 98

// ---------------- device scratch (allocation-free rule) ----------------
__device__ float g_Sx[N_NODES * HDIM];
__device__ float g_Se[N_NODES * EDIM];
__device__ int   g_deg[N_NODES];
__device__ int   g_off[N_NODES];
__device__ int   g_bsum[NB];
__device__ int2  g_rec[N_EDGES];
__device__ __nv_bfloat16 g_Wt_hi[HDIM * KDIM];  // [j][k] = Wcat[k][j] hi
__device__ __nv_bfloat16 g_Wt_lo[HDIM * KDIM];  // residual lo

// ---------------- helpers ----------------
__device__ __forceinline__ uint32_t smem_u32(const void* p) {
    uint32_t a;
    asm("{ .reg .u64 t; cvta.to.shared.u64 t, %1; cvt.u32.u64 %0, t; }"
        : "=r"(a) : "l"(p));
    return a;
}
__device__ __forceinline__ uint32_t pk2(float a, float b) {
    __nv_bfloat162 t = __floats2bfloat162_rn(a, b);
    return *reinterpret_cast<uint32_t*>(&t);
}
__device__ __forceinline__ void ldsm_x4(uint32_t* r, uint32_t addr) {
    asm volatile("ldmatrix.sync.aligned.m8n8.x4.shared.b16 {%0,%1,%2,%3}, [%4];"
                 : "=r"(r[0]), "=r"(r[1]), "=r"(r[2]), "=r"(r[3]) : "r"(addr));
}
// NON-transposed x2: correct for n-major (W^T) B storage with row.col mma.
__device__ __forceinline__ void ldsm_x2(uint32_t* r, uint32_t addr) {
    asm volatile("ldmatrix.sync.aligned.m8n8.x2.shared.b16 {%0,%1}, [%2];"
                 : "=r"(r[0]), "=r"(r[1]) : "r"(addr));
}
__device__ __forceinline__ void mma16816(float* d, const uint32_t* a,
                                         const uint32_t* b) {
    asm volatile(
        "mma.sync.aligned.m16n8k16.row.col.f32.bf16.bf16.f32 "
        "{%0,%1,%2,%3}, {%4,%5,%6,%7}, {%8,%9}, {%0,%1,%2,%3};"
        : "+f"(d[0]), "+f"(d[1]), "+f"(d[2]), "+f"(d[3])
        : "r"(a[0]), "r"(a[1]), "r"(a[2]), "r"(a[3]), "r"(b[0]), "r"(b[1]));
}

// smem layout for GEMM kernel (bytes). Rows padded 32->40 bf16 (80B).
#define AHI 0
#define ALO 10240
#define BHI 20480
#define BLO 30720
#define BSO 40960
#define BMO 41472
#define SMEM_TOTAL 41984

// ===========================================================================
// prep: transpose + bf16-split concat weight -> g_Wt_hi/lo [128][288]
// ===========================================================================
__global__ void wsplit_kernel(const float* __restrict__ Wself,
                              const float* __restrict__ Wmsg) {
    int i = blockIdx.x * blockDim.x + threadIdx.x;
    if (i >= HDIM * KDIM) return;
    int j = i / KDIM, k = i % KDIM;
    float v = (k < HDIM) ? Wself[k * HDIM + j] : Wmsg[(k - HDIM) * HDIM + j];
    __nv_bfloat16 h = __float2bfloat16(v);
    g_Wt_hi[i] = h;
    g_Wt_lo[i] = __float2bfloat16(v - __bfloat162float(h));
}

// ===========================================================================
// histogram / scan / reorder / gather (unchanged from R2)
// ===========================================================================
__global__ void zero_hist_kernel() {
    int i = blockIdx.x * blockDim.x + threadIdx.x;
    if (i < N_NODES) g_deg[i] = 0;
}
__global__ void hist_kernel(const int* __restrict__ ei) {
    int e = blockIdx.x * blockDim.x + threadIdx.x;
    if (e < N_EDGES) atomicAdd(&g_deg[__ldg(&ei[N_EDGES + e])], 1);
}
__device__ __forceinline__ int warp_incl_scan(int v, int lane) {
#pragma unroll
    for (int d = 1; d < 32; d <<= 1) {
        int t = __shfl_up_sync(0xffffffffu, v, d);
        if (lane >= d) v += t;
    }
    return v;
}
__global__ void scan1_kernel() {
    __shared__ int wsum[32];
    int i = blockIdx.x * 1024 + threadIdx.x;
    int lane = threadIdx.x & 31, w = threadIdx.x >> 5;
    int v = (i < N_NODES) ? g_deg[i] : 0;
    int inc = warp_incl_scan(v, lane);
    if (lane == 31) wsum[w] = inc;
    __syncthreads();
    if (w == 0) {
        int s = wsum[lane];
        int si = warp_incl_scan(s, lane);
        wsum[lane] = si - s;
    }
    __syncthreads();
    int excl = inc - v + wsum[w];
    if (i < N_NODES) g_off[i] = excl;
    if (threadIdx.x == 1023) g_bsum[blockIdx.x] = excl + v;
}
__global__ void scan2_kernel() {
    __shared__ int wsum[4];
    int i = threadIdx.x;
    int lane = i & 31, w = i >> 5;
    int v = (i < NB) ? g_bsum[i] : 0;
    int inc = warp_incl_scan(v, lane);
    if (lane == 31) wsum[w] = inc;
    __syncthreads();
    if (i == 0) {
        int c = 0;
#pragma unroll
        for (int k = 0; k < 4; k++) { int t = wsum[k]; wsum[k] = c; c += t; }
    }
    __syncthreads();
    if (i < NB) g_bsum[i] = inc - v + wsum[w];
}
__global__ void scan3_kernel() {
    int i = blockIdx.x * 1024 + threadIdx.x;
    if (i < N_NODES) g_off[i] += g_bsum[blockIdx.x];
}
__global__ void reorder_kernel(const int* __restrict__ ei) {
    int e = blockIdx.x * blockDim.x + threadIdx.x;
    if (e >= N_EDGES) return;
    int src = __ldg(&ei[e]);
    int dst = __ldg(&ei[N_EDGES + e]);
    int pos = atomicAdd(&g_off[dst], 1);
    g_rec[pos] = make_int2(src, e);
}
__global__ void __launch_bounds__(256)
gather_kernel(const float* __restrict__ x, const float* __restrict__ ea) {
    int gw   = (blockIdx.x * blockDim.x + threadIdx.x) >> 5;
    int lane = threadIdx.x & 31;
    int nw   = (gridDim.x * blockDim.x) >> 5;
    for (int n = gw; n < N_NODES; n += nw) {
        int beg = (n == 0) ? 0 : __ldg(&g_off[n - 1]);
        int end = __ldg(&g_off[n]);
        float4 ax = make_float4(0.f, 0.f, 0.f, 0.f);
        float4 ae = make_float4(0.f, 0.f, 0.f, 0.f);
        int i = beg;
        for (; i + 1 < end; i += 2) {
            int2 r0 = __ldg(&g_rec[i]);
            int2 r1 = __ldg(&g_rec[i + 1]);
            float4 v0 = __ldg(&reinterpret_cast<const float4*>(x + (size_t)r0.x * HDIM)[lane]);
            float4 v1 = __ldg(&reinterpret_cast<const float4*>(x + (size_t)r1.x * HDIM)[lane]);
            ax.x += v0.x + v1.x; ax.y += v0.y + v1.y;
            ax.z += v0.z + v1.z; ax.w += v0.w + v1.w;
            if (lane < 8) {
                float4 w0 = __ldg(&reinterpret_cast<const float4*>(ea + (size_t)r0.y * EDIM)[lane]);
                float4 w1 = __ldg(&reinterpret_cast<const float4*>(ea + (size_t)r1.y * EDIM)[lane]);
                ae.x += w0.x + w1.x; ae.y += w0.y + w1.y;
                ae.z += w0.z + w1.z; ae.w += w0.w + w1.w;
            }
        }
        if (i < end) {
            int2 r0 = __ldg(&g_rec[i]);
            float4 v0 = __ldg(&reinterpret_cast<const float4*>(x + (size_t)r0.x * HDIM)[lane]);
            ax.x += v0.x; ax.y += v0.y; ax.z += v0.z; ax.w += v0.w;
            if (lane < 8) {
                float4 w0 = __ldg(&reinterpret_cast<const float4*>(ea + (size_t)r0.y * EDIM)[lane]);
                ae.x += w0.x; ae.y += w0.y; ae.z += w0.z; ae.w += w0.w;
            }
        }
        reinterpret_cast<float4*>(g_Sx + (size_t)n * HDIM)[lane] = ax;
        if (lane < 8)
            reinterpret_cast<float4*>(g_Se + (size_t)n * EDIM)[lane] = ae;
    }
}

// ===========================================================================
// mma.sync bf16 2-split GEMM: out = relu([x|Sx|Se] @ W + b_self + deg*b_msg)
// 128x128 tile per CTA, K=288 in 9 chunks of 32, register-prefetch pipeline.
// ===========================================================================
__global__ void __launch_bounds__(256)
node_gemm_mma(const float* __restrict__ x,
              const float* __restrict__ bself,
              const float* __restrict__ bmsg,
              float* __restrict__ out) {
    __shared__ __align__(16) unsigned char sm[SMEM_TOTAL];
    const uint32_t sbase = smem_u32(sm);

    const int tid = threadIdx.x;
    const int lane = tid & 31;
    const int wid = tid >> 5;
    const int warp_m = wid & 3;     // 4 warps along M (32 rows each)
    const int warp_n = wid >> 2;    // 2 warps along N (64 cols each)

    float* bs = reinterpret_cast<float*>(sm + BSO);
    float* bm = reinterpret_cast<float*>(sm + BMO);
    if (tid < HDIM) { bs[tid] = bself[tid]; bm[tid] = bmsg[tid]; }

    const int n0 = blockIdx.x * 128;

    // per-thread staging indices
    const int kp = tid & 15;            // A: float2 pair index within 32-k chunk
    const int arow0 = tid >> 4;         // A: base row (stride 16 over t)
    float2 av[8];                       // A prefetch regs
    uint4 bhv[2], blv[2];               // B prefetch regs

    float acc[2][8][4];
#pragma unroll
    for (int a = 0; a < 2; a++)
#pragma unroll
        for (int b = 0; b < 8; b++)
#pragma unroll
            for (int c = 0; c < 4; c++) acc[a][b][c] = 0.f;

    // ---- stage(c): global fp32/bf16 -> regs ----
    auto stage = [&](int c) {
        const int kb = c * 32;
        const float* asrc;
        int astr;
        if (kb < 128)      { asrc = x    + kb;       astr = HDIM; }
        else if (kb < 256) { asrc = g_Sx + kb - 128; astr = HDIM; }
        else               { asrc = g_Se;            astr = EDIM; }
#pragma unroll
        for (int t = 0; t < 8; t++) {
            int gn = n0 + arow0 + t * 16;
            av[t] = (gn < N_NODES)
                ? *reinterpret_cast<const float2*>(asrc + (size_t)gn * astr + kp * 2)
                : make_float2(0.f, 0.f);
        }
#pragma unroll
        for (int t = 0; t < 2; t++) {
            int q = tid + t * 256;
            int j = q >> 2, sub = q & 3;
            size_t o = (size_t)j * KDIM + kb + sub * 8;
            bhv[t] = *reinterpret_cast<const uint4*>(g_Wt_hi + o);
            blv[t] = *reinterpret_cast<const uint4*>(g_Wt_lo + o);
        }
    };
    // ---- commit(): regs -> smem (A converted to bf16 hi/lo) ----
    auto commit = [&]() {
#pragma unroll
        for (int t = 0; t < 8; t++) {
            int row = arow0 + t * 16;
            float vx = av[t].x, vy = av[t].y;
            __nv_bfloat16 hx = __float2bfloat16(vx);
            __nv_bfloat16 hy = __float2bfloat16(vy);
            float lx = vx - __bfloat162float(hx);
            float ly = vy - __bfloat162float(hy);
            __nv_bfloat162 hp; hp.x = hx; hp.y = hy;
            *reinterpret_cast<uint32_t*>(sm + AHI + row * 80 + kp * 4) =
                *reinterpret_cast<uint32_t*>(&hp);
            *reinterpret_cast<uint32_t*>(sm + ALO + row * 80 + kp * 4) =
                pk2(lx, ly);
        }
#pragma unroll
        for (int t = 0; t < 2; t++) {
            int q = tid + t * 256;
            int j = q >> 2, sub = q & 3;
            *reinterpret_cast<uint4*>(sm + BHI + j * 80 + sub * 16) = bhv[t];
            *reinterpret_cast<uint4*>(sm + BLO + j * 80 + sub * 16) = blv[t];
        }
    };

    // ldmatrix per-thread base addresses
    const uint32_t a_row_off = (warp_m * 32 + (lane & 15)) * 80 + (lane >> 4) * 16;
    const uint32_t b_row_off = (warp_n * 64 + (lane & 7)) * 80 + ((lane >> 3) & 1) * 16;

    stage(0);
    __syncthreads();   // bias writes visible
    commit();
    __syncthreads();

    for (int c = 0; c < NCHUNK; c++) {
        if (c + 1 < NCHUNK) stage(c + 1);

#pragma unroll
        for (int ks = 0; ks < 2; ks++) {
            uint32_t ah[2][4], al[2][4];
#pragma unroll
            for (int mf = 0; mf < 2; mf++) {
                uint32_t ao = a_row_off + mf * 16 * 80 + ks * 32;
                ldsm_x4(ah[mf], sbase + AHI + ao);
                ldsm_x4(al[mf], sbase + ALO + ao);
            }
#pragma unroll
            for (int nf = 0; nf < 8; nf++) {
                uint32_t bo = b_row_off + nf * 8 * 80 + ks * 32;
                uint32_t bh[2], bl[2];
                ldsm_x2(bh, sbase + BHI + bo);
                ldsm_x2(bl, sbase + BLO + bo);
#pragma unroll
                for (int mf = 0; mf < 2; mf++) {
                    mma16816(acc[mf][nf], ah[mf], bh);
                    mma16816(acc[mf][nf], ah[mf], bl);
                    mma16816(acc[mf][nf], al[mf], bh);
                }
            }
        }
        __syncthreads();
        if (c + 1 < NCHUNK) {
            commit();
            __syncthreads();
        }
    }

    // ---- epilogue: bias + deg*b_msg + relu -> gmem ----
    const int gid = lane >> 2, tig = lane & 3;
#pragma unroll
    for (int mf = 0; mf < 2; mf++) {
#pragma unroll
        for (int rr = 0; rr < 2; rr++) {
            int row = warp_m * 32 + mf * 16 + rr * 8 + gid;
            int gn = n0 + row;
            if (gn >= N_NODES) continue;
            float degf = (float)g_deg[gn];
#pragma unroll
            for (int nf = 0; nf < 8; nf++) {
                int j = warp_n * 64 + nf * 8 + tig * 2;
                float2 o;
                o.x = fmaxf(acc[mf][nf][rr * 2 + 0] + bs[j]     + degf * bm[j],     0.f);
                o.y = fmaxf(acc[mf][nf][rr * 2 + 1] + bs[j + 1] + degf * bm[j + 1], 0.f);
                *reinterpret_cast<float2*>(out + (size_t)gn * HDIM + j) = o;
            }
        }
    }
}

// ---------------------------------------------------------------------------
extern "C" void kernel_launch(void* const* d_in, const int* in_sizes, int n_in,
                              void* d_out, int out_size) {
    const float* x     = (const float*)d_in[0];
    const int*   ei    = (const int*)  d_in[1];
    const float* ea    = (const float*)d_in[2];
    const float* Wself = (const float*)d_in[3];
    const float* bself = (const float*)d_in[4];
    const float* Wmsg  = (const float*)d_in[5];
    const float* bmsg  = (const float*)d_in[6];
    float* out = (float*)d_out;

    wsplit_kernel<<<(HDIM * KDIM + 255) / 256, 256>>>(Wself, Wmsg);
    zero_hist_kernel<<<NB, 1024>>>();
    hist_kernel<<<(N_EDGES + 511) / 512, 512>>>(ei);
    scan1_kernel<<<NB, 1024>>>();
    scan2_kernel<<<1, 128>>>();
    scan3_kernel<<<NB, 1024>>>();
    reorder_kernel<<<(N_EDGES + 511) / 512, 512>>>(ei);
    gather_kernel<<<148 * 8, 256>>>(x, ea);
    node_gemm_mma<<<N_TILES, 256>>>(x, bself, bmsg, out);
}